// round 1
// baseline (speedup 1.0000x reference)
#include <cuda_runtime.h>

// out[b,c,h,w] = (1/256) * sum_{p,o in 0..8} input[b, p*9+o, h, w] * secondZ[b, c, h+p-4, w+o-4]
// B=8, C=256, H=W=128, 81 taps.

#define MD   4
#define WINW 9
#define NTAPS 81
#define HH 128
#define WW 128
#define CC 256

#define TH 8          // tile rows
#define TW 32         // tile cols
#define NPX 4         // pixels per thread (in w)
#define CB 32         // channels staged per iteration
#define NCP 16        // channel pairs staged (CB/2)
#define NCB (CC/CB)   // 8 channel blocks

#define SROW 41                 // float2 stride per s row (odd -> conflict-free phases)
#define SCP  (16*SROW)          // float2 per channel-pair plane (TH+8=16 rows)
#define WSM_FLOATS (NTAPS*TH*TW)   // 20736 floats = 82944 B
#define SSM_F2     (NCP*SCP)       // 10496 float2 = 83968 B
#define SMEM_BYTES (WSM_FLOATS*4 + SSM_F2*8)   // 166912 B

__device__ __forceinline__ unsigned long long splat2(float x) {
    unsigned long long r;
    asm("mov.b64 %0, {%1, %1};" : "=l"(r) : "f"(x));
    return r;
}
__device__ __forceinline__ void ffma2(unsigned long long& acc,
                                      unsigned long long a,
                                      unsigned long long b) {
    asm("fma.rn.f32x2 %0, %1, %2, %0;" : "+l"(acc) : "l"(a), "l"(b));
}
__device__ __forceinline__ float lo32(unsigned long long a) {
    return __uint_as_float((unsigned int)(a & 0xffffffffull));
}
__device__ __forceinline__ float hi32(unsigned long long a) {
    return __uint_as_float((unsigned int)(a >> 32));
}

__global__ void __launch_bounds__(256, 1)
corr_transpose_kernel(const float* __restrict__ inp,
                      const float* __restrict__ sec,
                      float* __restrict__ out)
{
    extern __shared__ float smem[];
    float*  wsm = smem;                                   // [81][TH][TW]
    float2* ssm = (float2*)(smem + WSM_FLOATS);           // [NCP][16][SROW]

    const int tid = threadIdx.x;
    const int cs  = tid >> 6;        // channel subgroup 0..3
    const int ty  = (tid >> 3) & 7;  // row 0..7
    const int tx  = tid & 7;         // col group 0..7  (x0 = 4*tx)
    const int gx  = blockIdx.x * TW;
    const int gy  = blockIdx.y * TH;
    const int b   = blockIdx.z;

    // ---- stage all 81 weight planes for this pixel tile (once per block) ----
    {
        const int total = NTAPS * TH * (TW / 4);   // 5184 float4 loads
        for (int idx = tid; idx < total; idx += 256) {
            int col4 = idx & 7;
            int rest = idx >> 3;
            int row  = rest & 7;
            int d    = rest >> 3;
            float4 v = *(const float4*)(inp + (((size_t)(b * NTAPS + d) * HH + gy + row) * WW + gx + col4 * 4));
            *(float4*)(wsm + (d * TH + row) * TW + col4 * 4) = v;
        }
    }

    const float scale = 1.0f / (float)CC;

    for (int cb = 0; cb < NCB; cb++) {
        __syncthreads();  // protect previous ssm reads

        // ---- stage 32 channels of second (channel-pair interleaved, with halo) ----
        {
            const int total = NCP * 16 * 40;   // 10240 float2 elems -> 40 per thread
            for (int idx = tid; idx < total; idx += 256) {
                int col  = idx % 40;
                int rest = idx / 40;
                int row  = rest & 15;
                int cp   = rest >> 4;
                int r  = gy + row - MD;
                int cc = gx + col - MD;
                float2 v = make_float2(0.0f, 0.0f);
                if ((unsigned)r < HH && (unsigned)cc < WW) {
                    const int c0 = cb * CB + 2 * cp;
                    const float* base = sec + (((size_t)(b * CC + c0) * HH + r) * WW + cc);
                    v.x = base[0];
                    v.y = base[HH * WW];
                }
                ssm[cp * SCP + row * SROW + col] = v;
            }
        }
        __syncthreads();

        // ---- compute: 4 px * 4 channel-pairs per thread ----
        unsigned long long acc[4][NPX];
        #pragma unroll
        for (int i = 0; i < 4; i++)
            #pragma unroll
            for (int j = 0; j < NPX; j++) acc[i][j] = 0ull;

        #pragma unroll 1
        for (int p = 0; p < 9; p++) {
            // weights for this p-row: 9 o-taps x 4 px, splatted to f32x2
            unsigned long long ws[9][NPX];
            const float* wrow = wsm + (p * 9) * (TH * TW) + ty * TW + 4 * tx;
            #pragma unroll
            for (int o = 0; o < 9; o++) {
                float4 wv = *(const float4*)(wrow + o * (TH * TW));
                ws[o][0] = splat2(wv.x);
                ws[o][1] = splat2(wv.y);
                ws[o][2] = splat2(wv.z);
                ws[o][3] = splat2(wv.w);
            }
            #pragma unroll
            for (int cpl = 0; cpl < 4; cpl++) {
                const int cpg = cs * 4 + cpl;
                const float2* srow = ssm + cpg * SCP + (ty + p) * SROW + 4 * tx;
                unsigned long long sw[12];
                #pragma unroll
                for (int j = 0; j < 12; j++)
                    sw[j] = *(const unsigned long long*)(srow + j);
                #pragma unroll
                for (int o = 0; o < 9; o++) {
                    #pragma unroll
                    for (int px = 0; px < NPX; px++)
                        ffma2(acc[cpl][px], ws[o][px], sw[o + px]);
                }
            }
        }

        // ---- store 8 channels x 4 px (two float4 per channel pair) ----
        #pragma unroll
        for (int cpl = 0; cpl < 4; cpl++) {
            const int c0 = cb * CB + (cs * 4 + cpl) * 2;
            float4 ev = make_float4(lo32(acc[cpl][0]) * scale, lo32(acc[cpl][1]) * scale,
                                    lo32(acc[cpl][2]) * scale, lo32(acc[cpl][3]) * scale);
            float4 od = make_float4(hi32(acc[cpl][0]) * scale, hi32(acc[cpl][1]) * scale,
                                    hi32(acc[cpl][2]) * scale, hi32(acc[cpl][3]) * scale);
            float* optr = out + (((size_t)(b * CC + c0) * HH + gy + ty) * WW + gx + 4 * tx);
            *(float4*)optr = ev;
            *(float4*)(optr + HH * WW) = od;
        }
    }
}

extern "C" void kernel_launch(void* const* d_in, const int* in_sizes, int n_in,
                              void* d_out, int out_size)
{
    const float* inp = (const float*)d_in[0];   // [B, 81, 128, 128]
    const float* sec = (const float*)d_in[1];   // [B, 256, 128, 128]
    float* out = (float*)d_out;                 // [B, 256, 128, 128]

    const int B = in_sizes[0] / (NTAPS * HH * WW);

    cudaFuncSetAttribute(corr_transpose_kernel,
                         cudaFuncAttributeMaxDynamicSharedMemorySize, SMEM_BYTES);

    dim3 grid(WW / TW, HH / TH, B);   // (4, 16, 8)
    corr_transpose_kernel<<<grid, 256, SMEM_BYTES>>>(inp, sec, out);
}

// round 2
// speedup vs baseline: 1.3306x; 1.3306x over previous
#include <cuda_runtime.h>

// out[b,c,h,w] = (1/256) * sum_{p,o in 0..8} inp[b, p*9+o, h, w] * sec[b, c, h+p-4, w+o-4]
// B=8, C=256, H=W=128.

#define MD 4
#define NTAPS 81
#define HH 128
#define WW 128
#define CC 256

#define TH 8
#define TW 32
#define CB 32                    // channels staged per iteration
#define NCB (CC/CB)              // 8
#define NCH 8                    // channels per thread

#define SSTR 44                  // staged row stride (floats): mult of 4 -> 16B aligned rows
#define SROWS 16                 // TH + 2*MD
#define SPLANE (SROWS*SSTR)      // 704 floats / channel
#define WSM_FLOATS (NTAPS*TH*TW) // 20736
#define SSM_FLOATS (CB*SPLANE)   // 22528
#define SMEM_BYTES ((WSM_FLOATS+SSM_FLOATS)*4)  // 173056 B

typedef unsigned long long u64;

__device__ __forceinline__ u64 pack2(float a, float b) {
    u64 r; asm("mov.b64 %0,{%1,%2};" : "=l"(r) : "f"(a), "f"(b)); return r;
}
__device__ __forceinline__ void ffma2(u64& acc, u64 a, u64 b) {
    asm("fma.rn.f32x2 %0, %1, %2, %0;" : "+l"(acc) : "l"(a), "l"(b));
}
__device__ __forceinline__ void lds_v2u64(u64& x, u64& y, unsigned addr) {
    asm volatile("ld.shared.v2.b64 {%0,%1},[%2];" : "=l"(x), "=l"(y) : "r"(addr));
}
__device__ __forceinline__ float lo32(u64 a) { return __uint_as_float((unsigned)(a & 0xffffffffull)); }
__device__ __forceinline__ float hi32(u64 a) { return __uint_as_float((unsigned)(a >> 32)); }

__global__ void __launch_bounds__(256, 1)
corr_transpose_kernel(const float* __restrict__ inp,
                      const float* __restrict__ sec,
                      float* __restrict__ out)
{
    extern __shared__ float smem[];
    float* wsm = smem;                  // [81][8][32]
    float* ssm = smem + WSM_FLOATS;     // [32 ch][16 rows][44]

    const int tid = threadIdx.x;
    const int tx  = tid & 7;            // pixel col group (4 px each)
    const int ty  = (tid >> 3) & 7;     // pixel row
    const int cs  = tid >> 6;           // channel subgroup 0..3
    const int gx  = blockIdx.x * TW;
    const int gy  = blockIdx.y * TH;
    const int b   = blockIdx.z;

    // ---- stage all 81 weight planes for this 8x32 tile (once) ----
    for (int idx = tid; idx < NTAPS * TH * (TW / 4); idx += 256) {
        int col4 = idx & 7;
        int rest = idx >> 3;
        int row  = rest & 7;
        int d    = rest >> 3;
        float4 v = *(const float4*)(inp + (((size_t)(b * NTAPS + d) * HH + gy + row) * WW + gx + col4 * 4));
        *(float4*)(wsm + (d * TH + row) * TW + col4 * 4) = v;
    }

    const unsigned wsm_addr = (unsigned)__cvta_generic_to_shared(wsm + ty * TW + 4 * tx);
    const float*   sbase    = ssm + (cs * NCH) * SPLANE + ty * SSTR + 4 * tx;
    const float scale = 1.0f / (float)CC;
    const int inner = tid & 7;          // 8 threads per staged channel
    const int sch   = tid >> 3;         // staged channel 0..31

    for (int cb = 0; cb < NCB; cb++) {
        __syncthreads();   // previous compute done before restaging

        // ---- stage 32 channels of sec with halo, float4 granularity ----
        {
            const float* gsec = sec + ((size_t)(b * CC + cb * CB + sch) * HH) * WW;
            float* plane = ssm + sch * SPLANE;
            #pragma unroll
            for (int rr = 0; rr < 2; rr++) {
                int row = inner * 2 + rr;
                int r = gy + row - MD;
                #pragma unroll
                for (int c4 = 0; c4 < 10; c4++) {
                    int c = gx - MD + 4 * c4;
                    float4 v = make_float4(0.f, 0.f, 0.f, 0.f);
                    if ((unsigned)r < HH) {
                        if (c >= 0 && c <= WW - 4) {
                            v = *(const float4*)(gsec + (size_t)r * WW + c);
                        } else {
                            const float* gr = gsec + (size_t)r * WW;
                            if ((unsigned)(c + 0) < WW) v.x = gr[c + 0];
                            if ((unsigned)(c + 1) < WW) v.y = gr[c + 1];
                            if ((unsigned)(c + 2) < WW) v.z = gr[c + 2];
                            if ((unsigned)(c + 3) < WW) v.w = gr[c + 3];
                        }
                    }
                    *(float4*)(plane + row * SSTR + 4 * c4) = v;
                }
            }
        }
        __syncthreads();

        // ---- compute: 8 channels x 4 px (2 pixel-pairs) per thread ----
        u64 acc[NCH][2];
        #pragma unroll
        for (int j = 0; j < NCH; j++) { acc[j][0] = 0ull; acc[j][1] = 0ull; }

        #pragma unroll 1
        for (int p = 0; p < 9; p++) {
            // weights: 9 taps x 2 pixel-pairs, loaded as aligned 128-bit pairs
            u64 wp[9][2];
            #pragma unroll
            for (int o = 0; o < 9; o++)
                lds_v2u64(wp[o][0], wp[o][1], wsm_addr + (unsigned)(((p * 9 + o) * TH * TW) << 2));

            #pragma unroll
            for (int j = 0; j < NCH; j++) {
                const float4* srow = (const float4*)(sbase + j * SPLANE + p * SSTR);
                float4 v0 = srow[0];
                float4 v1 = srow[1];
                float4 v2 = srow[2];
                // aligned pairs a[0..5], misaligned pairs m[0..4]
                u64 a0 = pack2(v0.x, v0.y), a1 = pack2(v0.z, v0.w);
                u64 a2 = pack2(v1.x, v1.y), a3 = pack2(v1.z, v1.w);
                u64 a4 = pack2(v2.x, v2.y), a5 = pack2(v2.z, v2.w);
                u64 m0 = pack2(v0.y, v0.z), m1 = pack2(v0.w, v1.x);
                u64 m2 = pack2(v1.y, v1.z), m3 = pack2(v1.w, v2.x);
                u64 m4 = pack2(v2.y, v2.z);
                u64 A[6] = {a0, a1, a2, a3, a4, a5};
                u64 M[5] = {m0, m1, m2, m3, m4};
                #pragma unroll
                for (int o = 0; o < 9; o++) {
                    u64 s0, s1;
                    if ((o & 1) == 0) { s0 = A[o >> 1]; s1 = A[(o >> 1) + 1]; }
                    else              { s0 = M[o >> 1]; s1 = M[(o >> 1) + 1]; }
                    ffma2(acc[j][0], wp[o][0], s0);
                    ffma2(acc[j][1], wp[o][1], s1);
                }
            }
        }

        // ---- store 8 channels x 4 px ----
        #pragma unroll
        for (int j = 0; j < NCH; j++) {
            int c = cb * CB + cs * NCH + j;
            float4 o4 = make_float4(lo32(acc[j][0]) * scale, hi32(acc[j][0]) * scale,
                                    lo32(acc[j][1]) * scale, hi32(acc[j][1]) * scale);
            *(float4*)(out + (((size_t)(b * CC + c) * HH + gy + ty) * WW + gx + 4 * tx)) = o4;
        }
    }
}

extern "C" void kernel_launch(void* const* d_in, const int* in_sizes, int n_in,
                              void* d_out, int out_size)
{
    const float* inp = (const float*)d_in[0];   // [B, 81, 128, 128]
    const float* sec = (const float*)d_in[1];   // [B, 256, 128, 128]
    float* out = (float*)d_out;                 // [B, 256, 128, 128]

    const int B = in_sizes[0] / (NTAPS * HH * WW);

    cudaFuncSetAttribute(corr_transpose_kernel,
                         cudaFuncAttributeMaxDynamicSharedMemorySize, SMEM_BYTES);

    dim3 grid(WW / TW, HH / TH, B);   // (4, 16, 8)
    corr_transpose_kernel<<<grid, 256, SMEM_BYTES>>>(inp, sec, out);
}

// round 3
// speedup vs baseline: 1.3469x; 1.0122x over previous
#include <cuda_runtime.h>

// out[b,c,h,w] = (1/256) * sum_{p,o in 0..8} inp[b, p*9+o, h, w] * sec[b, c, h+p-4, w+o-4]
// B=8, C=256, H=W=128.

#define MD 4
#define NTAPS 81
#define HH 128
#define WW 128
#define CC 256

#define TH 8
#define TW 32
#define CB 32                    // channels staged per iteration
#define NCB (CC/CB)              // 8
#define NCH 4                    // channels per thread (512 threads)

#define SSTR 44                  // staged row stride (floats): mult of 4 -> 16B aligned rows
#define SROWS 16                 // TH + 2*MD
#define SPLANE (SROWS*SSTR)      // 704 floats / channel
#define WSM_FLOATS (NTAPS*TH*TW) // 20736
#define SSM_FLOATS (CB*SPLANE)   // 22528
#define SMEM_BYTES ((WSM_FLOATS+SSM_FLOATS)*4)  // 173056 B

#define NT 512

typedef unsigned long long u64;

__device__ __forceinline__ u64 pack2(float a, float b) {
    u64 r; asm("mov.b64 %0,{%1,%2};" : "=l"(r) : "f"(a), "f"(b)); return r;
}
__device__ __forceinline__ void ffma2(u64& acc, u64 a, u64 b) {
    asm("fma.rn.f32x2 %0, %1, %2, %0;" : "+l"(acc) : "l"(a), "l"(b));
}
__device__ __forceinline__ void lds_v2u64(u64& x, u64& y, unsigned addr) {
    asm volatile("ld.shared.v2.b64 {%0,%1},[%2];" : "=l"(x), "=l"(y) : "r"(addr));
}
__device__ __forceinline__ float lo32(u64 a) { return __uint_as_float((unsigned)(a & 0xffffffffull)); }
__device__ __forceinline__ float hi32(u64 a) { return __uint_as_float((unsigned)(a >> 32)); }

__global__ void __launch_bounds__(NT, 1)
corr_transpose_kernel(const float* __restrict__ inp,
                      const float* __restrict__ sec,
                      float* __restrict__ out)
{
    extern __shared__ float smem[];
    float* wsm = smem;                  // [81][8][32]
    float* ssm = smem + WSM_FLOATS;     // [32 ch][16 rows][44]

    const int tid = threadIdx.x;
    const int tx  = tid & 7;            // pixel col group (4 px each)
    const int ty  = (tid >> 3) & 7;     // pixel row
    const int cs  = tid >> 6;           // channel subgroup 0..7
    const int gx  = blockIdx.x * TW;
    const int gy  = blockIdx.y * TH;
    const int b   = blockIdx.z;

    // ---- stage all 81 weight planes for this 8x32 tile (once) ----
    for (int idx = tid; idx < NTAPS * TH * (TW / 4); idx += NT) {
        int col4 = idx & 7;
        int rest = idx >> 3;
        int row  = rest & 7;
        int d    = rest >> 3;
        float4 v = *(const float4*)(inp + (((size_t)(b * NTAPS + d) * HH + gy + row) * WW + gx + col4 * 4));
        *(float4*)(wsm + (d * TH + row) * TW + col4 * 4) = v;
    }

    const unsigned wsm_addr = (unsigned)__cvta_generic_to_shared(wsm + ty * TW + 4 * tx);
    const float*   sbase    = ssm + (cs * NCH) * SPLANE + ty * SSTR + 4 * tx;
    const float scale = 1.0f / (float)CC;
    const int srow_t = tid & 15;        // staging row 0..15
    const int sch    = tid >> 4;        // staged channel 0..31

    for (int cb = 0; cb < NCB; cb++) {
        __syncthreads();   // previous compute done before restaging

        // ---- stage 32 channels of sec with halo, float4 granularity ----
        {
            const float* gsec = sec + ((size_t)(b * CC + cb * CB + sch) * HH) * WW;
            float* plane = ssm + sch * SPLANE;
            int r = gy + srow_t - MD;
            #pragma unroll
            for (int c4 = 0; c4 < 10; c4++) {
                int c = gx - MD + 4 * c4;
                float4 v = make_float4(0.f, 0.f, 0.f, 0.f);
                if ((unsigned)r < HH) {
                    if (c >= 0 && c <= WW - 4) {
                        v = *(const float4*)(gsec + (size_t)r * WW + c);
                    } else {
                        const float* gr = gsec + (size_t)r * WW;
                        if ((unsigned)(c + 0) < WW) v.x = gr[c + 0];
                        if ((unsigned)(c + 1) < WW) v.y = gr[c + 1];
                        if ((unsigned)(c + 2) < WW) v.z = gr[c + 2];
                        if ((unsigned)(c + 3) < WW) v.w = gr[c + 3];
                    }
                }
                *(float4*)(plane + srow_t * SSTR + 4 * c4) = v;
            }
        }
        __syncthreads();

        // ---- compute: 4 channels x 4 px (2 pixel-pairs) per thread ----
        u64 acc[NCH][2];
        #pragma unroll
        for (int j = 0; j < NCH; j++) { acc[j][0] = 0ull; acc[j][1] = 0ull; }

        #pragma unroll 1
        for (int p = 0; p < 9; p++) {
            // weights: 9 taps x 2 pixel-pairs, loaded as aligned 128-bit pairs
            u64 wp[9][2];
            #pragma unroll
            for (int o = 0; o < 9; o++)
                lds_v2u64(wp[o][0], wp[o][1], wsm_addr + (unsigned)(((p * 9 + o) * TH * TW) << 2));

            #pragma unroll
            for (int j = 0; j < NCH; j++) {
                const float4* srow = (const float4*)(sbase + j * SPLANE + p * SSTR);
                float4 v0 = srow[0];
                float4 v1 = srow[1];
                float4 v2 = srow[2];
                // aligned pairs a[0..5], misaligned pairs m[0..4]
                u64 a0 = pack2(v0.x, v0.y), a1 = pack2(v0.z, v0.w);
                u64 a2 = pack2(v1.x, v1.y), a3 = pack2(v1.z, v1.w);
                u64 a4 = pack2(v2.x, v2.y), a5 = pack2(v2.z, v2.w);
                u64 m0 = pack2(v0.y, v0.z), m1 = pack2(v0.w, v1.x);
                u64 m2 = pack2(v1.y, v1.z), m3 = pack2(v1.w, v2.x);
                u64 m4 = pack2(v2.y, v2.z);
                u64 A[6] = {a0, a1, a2, a3, a4, a5};
                u64 M[5] = {m0, m1, m2, m3, m4};
                #pragma unroll
                for (int o = 0; o < 9; o++) {
                    u64 s0, s1;
                    if ((o & 1) == 0) { s0 = A[o >> 1]; s1 = A[(o >> 1) + 1]; }
                    else              { s0 = M[o >> 1]; s1 = M[(o >> 1) + 1]; }
                    ffma2(acc[j][0], wp[o][0], s0);
                    ffma2(acc[j][1], wp[o][1], s1);
                }
            }
        }

        // ---- store 4 channels x 4 px ----
        #pragma unroll
        for (int j = 0; j < NCH; j++) {
            int c = cb * CB + cs * NCH + j;
            float4 o4 = make_float4(lo32(acc[j][0]) * scale, hi32(acc[j][0]) * scale,
                                    lo32(acc[j][1]) * scale, hi32(acc[j][1]) * scale);
            *(float4*)(out + (((size_t)(b * CC + c) * HH + gy + ty) * WW + gx + 4 * tx)) = o4;
        }
    }
}

extern "C" void kernel_launch(void* const* d_in, const int* in_sizes, int n_in,
                              void* d_out, int out_size)
{
    const float* inp = (const float*)d_in[0];   // [B, 81, 128, 128]
    const float* sec = (const float*)d_in[1];   // [B, 256, 128, 128]
    float* out = (float*)d_out;                 // [B, 256, 128, 128]

    const int B = in_sizes[0] / (NTAPS * HH * WW);

    cudaFuncSetAttribute(corr_transpose_kernel,
                         cudaFuncAttributeMaxDynamicSharedMemorySize, SMEM_BYTES);

    dim3 grid(WW / TW, HH / TH, B);   // (4, 16, 8)
    corr_transpose_kernel<<<grid, NT, SMEM_BYTES>>>(inp, sec, out);
}